// round 5
// baseline (speedup 1.0000x reference)
#include <cuda_runtime.h>

#define IMG_H 4200
#define IMG_W 3200
#define HF 84
#define WF 64
#define NB 8
#define STRIDE_PX 50
#define ROW_F2 (IMG_W / 2)      // 1600 float2 per image row
#define GRP_F2 2500             // 2 tiles * 1250 float2

// scratch: conv1 output feats [NB, 2, HF, WF]  (344 KB)
__device__ float g_feats[NB * 2 * HF * WF];

// ---------------------------------------------------------------------------
// Kernel 1: 50x50 stride-50 VALID conv, 1->2 ch (non-overlapping patches).
// Round = 2-tile group (tx0 even): group rows are 50 contiguous float2
// (400 B, 16B-aligned) -> near-perfect sector efficiency. Thread element
// q = t + 256*j, j=0..9; tile = (q%50)>=25 is static per (t,j) -> predicated
// accumulate into 4 registers. Weights in registers. Double-buffered
// cross-warp reduce, one barrier per round.
// ---------------------------------------------------------------------------
__global__ __launch_bounds__(256, 4) void conv1_kernel(const float* __restrict__ X,
                                                       const float* __restrict__ w,
                                                       const float* __restrict__ b)
{
    const int t = threadIdx.x;

    float2 w0[10], w1[10];
    int    off[10];
    bool   sel[10];
    const float2* wv0 = (const float2*)w;              // ch0: 1250 float2
    const float2* wv1 = (const float2*)(w + 2500);     // ch1
#pragma unroll
    for (int j = 0; j < 10; j++) {
        const int q   = t + j * 256;
        const bool ok = (q < GRP_F2);
        const int row = q / 50;           // 50 f2 per 2-tile row segment
        const int col = q % 50;
        const bool s  = (col >= 25);      // which tile of the pair
        const int wcol = col - (s ? 25 : 0);
        w0[j]  = ok ? wv0[row * 25 + wcol] : make_float2(0.f, 0.f);
        w1[j]  = ok ? wv1[row * 25 + wcol] : make_float2(0.f, 0.f);
        off[j] = ok ? (row * ROW_F2 + col) : 0;
        sel[j] = s;
    }
    const float b0 = b[0], b1 = b[1];

    __shared__ float red[2][8][4];   // [buf][warp][tile*2+ch]

    const int warp = t >> 5;
    const int total_rounds = NB * HF * WF / 2;  // 21504 2-tile groups
    int buf = 0;

    for (int r = blockIdx.x; r < total_rounds; r += gridDim.x, buf ^= 1) {
        const int tile0 = r * 2;
        const int tx0 = tile0 % WF;              // even
        const int ty  = (tile0 / WF) % HF;
        const int n   = tile0 / (WF * HF);

        const float2* base = (const float2*)X
            + (size_t)n * (IMG_H * ROW_F2)
            + (size_t)(ty * STRIDE_PX) * ROW_F2
            + tx0 * 25;

        float a0 = 0.f, a1 = 0.f, c0 = 0.f, c1 = 0.f;  // tile0(ch0,ch1), tile1(ch0,ch1)
#pragma unroll
        for (int j = 0; j < 10; j++) {
            const float2 xv = __ldg(base + off[j]);
            const float p0 = xv.x * w0[j].x + xv.y * w0[j].y;
            const float p1 = xv.x * w1[j].x + xv.y * w1[j].y;
            if (sel[j]) { c0 += p0; c1 += p1; }
            else        { a0 += p0; a1 += p1; }
        }

        // warp reduce: 4 independent shfl chains
#pragma unroll
        for (int s = 16; s > 0; s >>= 1) {
            a0 += __shfl_down_sync(0xffffffffu, a0, s);
            a1 += __shfl_down_sync(0xffffffffu, a1, s);
            c0 += __shfl_down_sync(0xffffffffu, c0, s);
            c1 += __shfl_down_sync(0xffffffffu, c1, s);
        }
        if ((t & 31) == 0) {
            red[buf][warp][0] = a0;
            red[buf][warp][1] = a1;
            red[buf][warp][2] = c0;
            red[buf][warp][3] = c1;
        }
        __syncthreads();   // only barrier this round (buffers alternate)

        if (t < 32) {
            const int o = t >> 3;          // output 0..3 = tile*2+ch
            const int k = t & 7;           // warp index
            float v = red[buf][k][o];
            v += __shfl_down_sync(0xffffffffu, v, 4, 8);
            v += __shfl_down_sync(0xffffffffu, v, 2, 8);
            v += __shfl_down_sync(0xffffffffu, v, 1, 8);
            if (k == 0) {
                const int tile = o >> 1, ch = o & 1;
                g_feats[((n * 2 + ch) * HF + ty) * WF + (tx0 + tile)] =
                    v + (ch ? b1 : b0);
            }
        }
    }
}

// ---------------------------------------------------------------------------
// Kernel 2: fused head. One thread per (position, anchor): block = 64 pos
// (one feature row) x 9 anchors = 576 threads; grid = 8*84 = 672 blocks.
// Feats rows y-1..y+1 staged in smem; cls mask computed per thread (cheap
// redundancy); outputs are directly contiguous float4 stores (tid order
// matches output layout).
// ---------------------------------------------------------------------------
__global__ __launch_bounds__(576) void head_kernel(const float* __restrict__ box_w,
                                                   const float* __restrict__ box_b,
                                                   const float* __restrict__ cls_w,
                                                   const float* __restrict__ cls_b,
                                                   float4* __restrict__ out)
{
    __shared__ float s_bw[9][73];      // box_w padded: [anchor][4*18], stride 73
    __shared__ float s_bb[36];
    __shared__ float s_cw[36];         // cls_w [2,2,3,3]
    __shared__ float s_cb[2];
    __shared__ float s_f[2][3][64];    // feats ch x rows(y-1..y+1) x cols

    const int tid = threadIdx.x;
    const int n = blockIdx.x / HF;
    const int y = blockIdx.x % HF;

    // weights -> smem (bank-padded so 9 anchors hit 9 distinct banks)
    for (int i = tid; i < 9 * 73; i += 576) {
        const int a = i / 73, rsd = i % 73;
        if (rsd < 72) s_bw[a][rsd] = box_w[a * 72 + rsd];
    }
    if (tid < 36) {
        s_bb[tid] = box_b[tid];
        s_cw[tid] = cls_w[tid];
    }
    if (tid < 2) s_cb[tid] = cls_b[tid];

    // stage feats rows y-1..y+1 (zero-padded): 384 elements
    if (tid < 384) {
        const int xx = tid & 63;
        const int rr = (tid >> 6) % 3;
        const int ic = tid / 192;
        const int yy = y - 1 + rr;
        float v = 0.0f;
        if (yy >= 0 && yy < HF)
            v = g_feats[((n * 2 + ic) * HF + yy) * WF + xx];
        s_f[ic][rr][xx] = v;
    }
    __syncthreads();

    const int x = tid / 9;     // position in row
    const int a = tid % 9;     // anchor

    // gather 3x3x2 neighborhood from smem (x edges zero-padded)
    float f[18];
#pragma unroll
    for (int ic = 0; ic < 2; ic++) {
#pragma unroll
        for (int dy = 0; dy < 3; dy++) {
#pragma unroll
            for (int dx = 0; dx < 3; dx++) {
                const int xx = x + dx - 1;
                float v = 0.0f;
                if (xx >= 0 && xx < WF) v = s_f[ic][dy][xx];
                f[ic * 9 + dy * 3 + dx] = v;
            }
        }
    }

    // cls conv + 2-channel softmax threshold (redundant per anchor, cheap)
    float cc0 = s_cb[0], cc1 = s_cb[1];
#pragma unroll
    for (int k = 0; k < 18; k++) {
        cc0 += f[k] * s_cw[k];
        cc1 += f[k] * s_cw[18 + k];
    }
    const float m  = fmaxf(cc0, cc1);
    const float e0 = __expf(cc0 - m), e1 = __expf(cc1 - m);
    const float p1 = e1 / (e0 + e1);
    const float mval = (p1 > 0.95f) ? 1.0f : 0.0f;

    // box conv for this thread's anchor: 4 output channels
    float o0 = s_bb[a * 4 + 0], o1 = s_bb[a * 4 + 1];
    float o2 = s_bb[a * 4 + 2], o3 = s_bb[a * 4 + 3];
    const float* wp = &s_bw[a][0];
#pragma unroll
    for (int kk = 0; kk < 18; kk++) {
        const float fv = f[kk];
        o0 += fv * wp[kk];
        o1 += fv * wp[18 + kk];
        o2 += fv * wp[36 + kk];
        o3 += fv * wp[54 + kk];
    }

    const float SZ[3] = {16.0f, 32.0f, 64.0f};
    const float RI[3] = {0.70710678118654752f, 1.0f, 1.41421356237309505f};
    const float s  = SZ[a / 3];
    const float r  = RI[a % 3];
    const float wa = (s / r) * 0.5f;
    const float ha = (s * r) * 0.5f;
    const float gx = ((float)x + 0.5f) * (float)STRIDE_PX;
    const float gy = ((float)y + 0.5f) * (float)STRIDE_PX;

    const float v0 = fminf(fmaxf(gx - wa + o0, 0.0f), (float)IMG_W);
    const float v1 = fminf(fmaxf(gy - ha + o1, 0.0f), (float)IMG_H);
    const float v2 = fminf(fmaxf(gx + wa + o2, 0.0f), (float)IMG_W);
    const float v3 = fminf(fmaxf(gy + ha + o3, 0.0f), (float)IMG_H);

    // tid order == output order: fully contiguous float4 stores
    out[(size_t)blockIdx.x * 576 + tid] =
        make_float4(v0 * mval, v1 * mval, v2 * mval, v3 * mval);
}

extern "C" void kernel_launch(void* const* d_in, const int* in_sizes, int n_in,
                              void* d_out, int out_size)
{
    const float* X      = (const float*)d_in[0];
    const float* conv_w = (const float*)d_in[1];
    const float* conv_b = (const float*)d_in[2];
    const float* box_w  = (const float*)d_in[3];
    const float* box_b  = (const float*)d_in[4];
    const float* cls_w  = (const float*)d_in[5];
    const float* cls_b  = (const float*)d_in[6];
    float4* out = (float4*)d_out;

    // persistent single-wave grid, grid-stride over 21504 2-tile rounds
    conv1_kernel<<<592, 256>>>(X, conv_w, conv_b);
    // 672 blocks (one per feature row) x 576 threads (64 pos x 9 anchors)
    head_kernel<<<672, 576>>>(box_w, box_b, cls_w, cls_b, out);
}

// round 6
// speedup vs baseline: 1.0663x; 1.0663x over previous
#include <cuda_runtime.h>

#define IMG_H 4200
#define IMG_W 3200
#define HF 84
#define WF 64
#define NB 8
#define ROW_F2 (IMG_W / 2)      // 1600 float2 per image row

// scratch: conv1 output feats [NB, 2, HF, WF]  (344 KB)
__device__ float g_feats[NB * 2 * HF * WF];

// ---------------------------------------------------------------------------
// Kernel 1: 50x50 stride-50 VALID conv, 1->2 ch (non-overlapping patches).
// Round = 8-tile row group. Group image rows are 200 contiguous float2
// (1600 B = 50 whole sectors, 1600 B-aligned) -> 100% sector efficiency.
// Thread t owns f2-column c=t (c<200): tile c/25 is STATIC -> 2 accumulators,
// low regs, no spills. Weights: packed float4 in smem, 1 LDS.128/row.
// Reduction: smem partials + 16-thread 25-sum; double-buffered, 1 bar/round.
// ---------------------------------------------------------------------------
__global__ __launch_bounds__(256) void conv1_kernel(const float* __restrict__ X,
                                                    const float* __restrict__ w,
                                                    const float* __restrict__ b)
{
    __shared__ float4 s_w[1250];            // [row*25+wc] = {w0.x,w0.y,w1.x,w1.y}
    __shared__ float  s_part[2][2][200];    // [buf][ch][col]

    const int t = threadIdx.x;
    const float2* wv0 = (const float2*)w;           // ch0: 1250 float2
    const float2* wv1 = (const float2*)(w + 2500);  // ch1
    for (int i = t; i < 1250; i += 256) {
        const float2 p0 = wv0[i];
        const float2 p1 = wv1[i];
        s_w[i] = make_float4(p0.x, p0.y, p1.x, p1.y);
    }
    const float b0 = b[0], b1 = b[1];
    __syncthreads();

    const int  c      = t;            // f2 column within 8-tile group
    const bool active = (c < 200);
    const int  wc     = c % 25;       // weight f2-column
    int buf = 0;

    const int rounds = NB * HF * WF / 8;   // 5376
    for (int r = blockIdx.x; r < rounds; r += gridDim.x, buf ^= 1) {
        const int tile0 = r * 8;
        const int tx0 = tile0 % WF;               // multiple of 8
        const int ty  = (tile0 / WF) % HF;
        const int n   = tile0 / (WF * HF);

        float a0 = 0.f, a1 = 0.f;
        if (active) {
            const float2* base = (const float2*)X
                + (size_t)n * (IMG_H * ROW_F2)
                + (size_t)(ty * 50) * ROW_F2
                + tx0 * 25 + c;
#pragma unroll 10
            for (int row = 0; row < 50; row++) {
                const float2 xv = __ldg(base + row * ROW_F2);
                const float4 ww = s_w[row * 25 + wc];
                a0 += xv.x * ww.x + xv.y * ww.y;
                a1 += xv.x * ww.z + xv.y * ww.w;
            }
            s_part[buf][0][c] = a0;
            s_part[buf][1][c] = a1;
        }
        __syncthreads();   // only barrier this round (buffers alternate)

        if (t < 16) {
            const int tile = t >> 1, ch = t & 1;
            float s = 0.f;
#pragma unroll
            for (int k = 0; k < 25; k++) s += s_part[buf][ch][tile * 25 + k];
            g_feats[((n * 2 + ch) * HF + ty) * WF + (tx0 + tile)] =
                s + (ch ? b1 : b0);
        }
    }
}

// ---------------------------------------------------------------------------
// Kernel 2: fused head. Block = one feature row: 9 anchors x 64 positions,
// tid = a*64 + x  ->  each WARP has a single anchor, so all box-weight LDS
// are uniform-address broadcasts. f-gather from smem is conflict-free
// (consecutive x). Output re-linearized via padded smem stage -> contiguous
// float4 stores.
// ---------------------------------------------------------------------------
__global__ __launch_bounds__(576) void head_kernel(const float* __restrict__ box_w,
                                                   const float* __restrict__ box_b,
                                                   const float* __restrict__ cls_w,
                                                   const float* __restrict__ cls_b,
                                                   float4* __restrict__ out)
{
    __shared__ float  s_bw[9 * 72];     // box_w [anchor][4*18]
    __shared__ float  s_bb[36];
    __shared__ float  s_cw[36];         // cls_w [2,2,3,3]
    __shared__ float  s_cb[2];
    __shared__ float  s_f[2][3][64];    // feats ch x rows(y-1..y+1) x cols
    __shared__ float4 s_stage[9 * 65];  // [a*65 + x], padded vs bank conflicts

    const int tid = threadIdx.x;
    const int n = blockIdx.x / HF;
    const int y = blockIdx.x % HF;

    for (int i = tid; i < 9 * 72; i += 576) s_bw[i] = box_w[i];
    if (tid < 36) {
        s_bb[tid] = box_b[tid];
        s_cw[tid] = cls_w[tid];
    }
    if (tid < 2) s_cb[tid] = cls_b[tid];

    // stage feats rows y-1..y+1 (zero-padded): 384 elements
    if (tid < 384) {
        const int xx = tid & 63;
        const int rr = (tid >> 6) % 3;
        const int ic = tid / 192;
        const int yy = y - 1 + rr;
        float v = 0.0f;
        if (yy >= 0 && yy < HF)
            v = g_feats[((n * 2 + ic) * HF + yy) * WF + xx];
        s_f[ic][rr][xx] = v;
    }
    __syncthreads();

    const int a = tid >> 6;     // anchor: uniform within each warp
    const int x = tid & 63;     // position in row

    // gather 3x3x2 neighborhood from smem (x edges zero-padded)
    float f[18];
#pragma unroll
    for (int ic = 0; ic < 2; ic++) {
#pragma unroll
        for (int dy = 0; dy < 3; dy++) {
#pragma unroll
            for (int dx = 0; dx < 3; dx++) {
                const int xx = x + dx - 1;
                float v = 0.0f;
                if (xx >= 0 && xx < WF) v = s_f[ic][dy][xx];
                f[ic * 9 + dy * 3 + dx] = v;
            }
        }
    }

    // cls conv + 2-channel softmax threshold (redundant per anchor, cheap)
    float cc0 = s_cb[0], cc1 = s_cb[1];
#pragma unroll
    for (int k = 0; k < 18; k++) {
        cc0 += f[k] * s_cw[k];
        cc1 += f[k] * s_cw[18 + k];
    }
    const float m  = fmaxf(cc0, cc1);
    const float e0 = __expf(cc0 - m), e1 = __expf(cc1 - m);
    const float p1 = e1 / (e0 + e1);
    const float mval = (p1 > 0.95f) ? 1.0f : 0.0f;

    // box conv for this warp's anchor (weight reads warp-uniform -> broadcast)
    float o0 = s_bb[a * 4 + 0], o1 = s_bb[a * 4 + 1];
    float o2 = s_bb[a * 4 + 2], o3 = s_bb[a * 4 + 3];
    const float* wp = &s_bw[a * 72];
#pragma unroll
    for (int kk = 0; kk < 18; kk++) {
        const float fv = f[kk];
        o0 += fv * wp[kk];
        o1 += fv * wp[18 + kk];
        o2 += fv * wp[36 + kk];
        o3 += fv * wp[54 + kk];
    }

    const float SZ[3] = {16.0f, 32.0f, 64.0f};
    const float RI[3] = {0.70710678118654752f, 1.0f, 1.41421356237309505f};
    const float s  = SZ[a / 3];
    const float r  = RI[a % 3];
    const float wa = (s / r) * 0.5f;
    const float ha = (s * r) * 0.5f;
    const float gx = ((float)x + 0.5f) * 50.0f;
    const float gy = ((float)y + 0.5f) * 50.0f;

    const float v0 = fminf(fmaxf(gx - wa + o0, 0.0f), (float)IMG_W);
    const float v1 = fminf(fmaxf(gy - ha + o1, 0.0f), (float)IMG_H);
    const float v2 = fminf(fmaxf(gx + wa + o2, 0.0f), (float)IMG_W);
    const float v3 = fminf(fmaxf(gy + ha + o3, 0.0f), (float)IMG_H);

    s_stage[a * 65 + x] = make_float4(v0 * mval, v1 * mval, v2 * mval, v3 * mval);
    __syncthreads();

    // linearize: out element i (= x*9 + a) <- s_stage[(i%9)*65 + i/9]
    float4* bout = out + (size_t)blockIdx.x * 576;
    const int aa = tid % 9, xx = tid / 9;
    bout[tid] = s_stage[aa * 65 + xx];
}

extern "C" void kernel_launch(void* const* d_in, const int* in_sizes, int n_in,
                              void* d_out, int out_size)
{
    const float* X      = (const float*)d_in[0];
    const float* conv_w = (const float*)d_in[1];
    const float* conv_b = (const float*)d_in[2];
    const float* box_w  = (const float*)d_in[3];
    const float* box_b  = (const float*)d_in[4];
    const float* cls_w  = (const float*)d_in[5];
    const float* cls_b  = (const float*)d_in[6];
    float4* out = (float4*)d_out;

    // persistent grid, grid-stride over 5376 8-tile rounds
    conv1_kernel<<<592, 256>>>(X, conv_w, conv_b);
    // 672 blocks (one per feature row) x 576 threads (9 anchors x 64 pos)
    head_kernel<<<672, 576>>>(box_w, box_b, cls_w, cls_b, out);
}

// round 7
// speedup vs baseline: 1.4632x; 1.3722x over previous
#include <cuda_runtime.h>

#define IMG_H 4200
#define IMG_W 3200
#define HF 84
#define WF 64
#define NB 8
#define ROW_F2 (IMG_W / 2)           // 1600 float2 per image row
#define FEAT (NB * 2 * HF * WF)      // 86016

// conv1 partial sums per row-chunk: [chunk][n][ch][ty][tx]  (1.72 MB)
__device__ float g_part[5][FEAT];

// ---------------------------------------------------------------------------
// Kernel 1: 50x50 stride-50 VALID conv, 1->2 ch (non-overlapping patches).
// Block owns row-chunk = blockIdx.x % 5 (10 of the 50 tile rows) -> thread's
// weights are just 10 float4 in REGISTERS (w0.x,w0.y,w1.x,w1.y per row),
// loaded once. Work item = 4 consecutive 8-tile groups: image rows are
// 800 f2 = 6.4 KB contiguous, 1600B-aligned segments -> 100% sector
// efficiency. 40 independent LDG.64/thread/item. Reduction: smem partials,
// double-buffered, ONE barrier per item. 560 blocks x exactly 12 items.
// ---------------------------------------------------------------------------
__global__ __launch_bounds__(224, 4) void conv1_kernel(const float* __restrict__ X,
                                                       const float* __restrict__ w)
{
    __shared__ float s_part[2][8][200];   // [buf][group*2+ch][col]

    const int t      = threadIdx.x;
    const bool active = (t < 200);
    const int chunk  = blockIdx.x % 5;    // rows chunk*10 .. chunk*10+9
    const int qslot  = blockIdx.x / 5;    // 0..111

    // per-thread register weights: rows chunk*10+r, f2-col (t%25)
    const float2* wv0 = (const float2*)w;           // ch0: 1250 f2
    const float2* wv1 = (const float2*)(w + 2500);  // ch1
    const int wc = t % 25;
    float4 wr[10];
#pragma unroll
    for (int r = 0; r < 10; r++) {
        const int wi = (chunk * 10 + r) * 25 + wc;
        const float2 p0 = active ? wv0[wi] : make_float2(0.f, 0.f);
        const float2 p1 = active ? wv1[wi] : make_float2(0.f, 0.f);
        wr[r] = make_float4(p0.x, p0.y, p1.x, p1.y);
    }

    int buf = 0;
    for (int it = 0; it < 12; it++, buf ^= 1) {
        const int q   = qslot * 12 + it;   // 0..1343 group-quads
        const int g0  = q * 4;             // first 8-tile group
        const int gx0 = g0 & 7;            // 0 or 4 (group within feature row)
        const int ty  = (g0 >> 3) % HF;
        const int n   = g0 / (8 * HF);

        if (active) {
            const float2* base = (const float2*)X
                + (size_t)n * (IMG_H * ROW_F2)
                + (size_t)(ty * 50 + chunk * 10) * ROW_F2
                + gx0 * 200 + t;

            float a[8];
#pragma unroll
            for (int k = 0; k < 8; k++) a[k] = 0.f;

#pragma unroll
            for (int r = 0; r < 10; r++) {
#pragma unroll
                for (int gg = 0; gg < 4; gg++) {
                    const float2 xv = __ldg(base + r * ROW_F2 + gg * 200);
                    a[gg * 2 + 0] += xv.x * wr[r].x + xv.y * wr[r].y;
                    a[gg * 2 + 1] += xv.x * wr[r].z + xv.y * wr[r].w;
                }
            }
#pragma unroll
            for (int k = 0; k < 8; k++) s_part[buf][k][t] = a[k];
        }
        __syncthreads();   // only barrier this item (buffers alternate)

        // 64 finalizer threads: t -> (ch = t>>5, gg = (t>>3)&3, tile = t&7)
        // so each warp stores 32 consecutive g_part floats (coalesced).
        if (t < 64) {
            const int ch = t >> 5, gg = (t >> 3) & 3, tile = t & 7;
            float s = 0.f;
#pragma unroll
            for (int k = 0; k < 25; k++)
                s += s_part[buf][gg * 2 + ch][tile * 25 + k];
            g_part[chunk][((n * 2 + ch) * HF + ty) * WF + (gx0 + gg) * 8 + tile] = s;
        }
    }
}

// ---------------------------------------------------------------------------
// Kernel 2: fused head. Block = one feature row: tid = a*64 + x (warp-uniform
// anchor). Staging sums the 5 conv1 partials + bias. Box weights packed as
// float4 (4 output channels per LDS.128), cls as float2 -> ~55 LDS/thread
// (was ~108). Output linearized via padded smem stage -> contiguous stores.
// ---------------------------------------------------------------------------
__global__ __launch_bounds__(576) void head_kernel(const float* __restrict__ conv_b,
                                                   const float* __restrict__ box_w,
                                                   const float* __restrict__ box_b,
                                                   const float* __restrict__ cls_w,
                                                   const float* __restrict__ cls_b,
                                                   float4* __restrict__ out)
{
    __shared__ float4 s_bwq[9 * 18];    // [a*18+k] = box_w ch 4a..4a+3 at k
    __shared__ float4 s_bb4[9];         // box bias per anchor
    __shared__ float2 s_cw2[18];        // cls_w both channels at k
    __shared__ float  s_cb[2];
    __shared__ float  s_f[2][3][64];    // feats ch x rows(y-1..y+1) x cols
    __shared__ float4 s_stage[9 * 65];  // [a*65+x], padded

    const int tid = threadIdx.x;
    const int n = blockIdx.x / HF;
    const int y = blockIdx.x % HF;

    if (tid < 162) {                    // transpose box_w: [36,18] -> [9][18]x4ch
        const int a = tid / 18, k = tid % 18;
        s_bwq[tid] = make_float4(box_w[(a * 4 + 0) * 18 + k],
                                 box_w[(a * 4 + 1) * 18 + k],
                                 box_w[(a * 4 + 2) * 18 + k],
                                 box_w[(a * 4 + 3) * 18 + k]);
    }
    if (tid < 9)  s_bb4[tid] = ((const float4*)box_b)[tid];
    if (tid < 18) s_cw2[tid] = make_float2(cls_w[tid], cls_w[18 + tid]);
    if (tid < 2)  s_cb[tid]  = cls_b[tid];

    // stage feats rows y-1..y+1 (zero-padded): sum 5 partials + bias
    if (tid < 384) {
        const int xx = tid & 63;
        const int rr = (tid >> 6) % 3;
        const int ic = tid / 192;
        const int yy = y - 1 + rr;
        float v = 0.0f;
        if (yy >= 0 && yy < HF) {
            const int idx = ((n * 2 + ic) * HF + yy) * WF + xx;
            v = conv_b[ic];
#pragma unroll
            for (int c = 0; c < 5; c++) v += g_part[c][idx];
        }
        s_f[ic][rr][xx] = v;
    }
    __syncthreads();

    const int a = tid >> 6;     // anchor: uniform within each warp
    const int x = tid & 63;     // position in row

    // gather 3x3x2 neighborhood from smem (x edges zero-padded)
    float f[18];
#pragma unroll
    for (int ic = 0; ic < 2; ic++) {
#pragma unroll
        for (int dy = 0; dy < 3; dy++) {
#pragma unroll
            for (int dx = 0; dx < 3; dx++) {
                const int xx = x + dx - 1;
                float v = 0.0f;
                if (xx >= 0 && xx < WF) v = s_f[ic][dy][xx];
                f[ic * 9 + dy * 3 + dx] = v;
            }
        }
    }

    // cls conv + softmax threshold
    float cc0 = s_cb[0], cc1 = s_cb[1];
#pragma unroll
    for (int k = 0; k < 18; k++) {
        const float2 cw = s_cw2[k];
        cc0 += f[k] * cw.x;
        cc1 += f[k] * cw.y;
    }
    const float m  = fmaxf(cc0, cc1);
    const float e0 = __expf(cc0 - m), e1 = __expf(cc1 - m);
    const float p1 = e1 / (e0 + e1);
    const float mval = (p1 > 0.95f) ? 1.0f : 0.0f;

    // box conv: 4 channels via float4 weights (warp-uniform -> broadcast LDS)
    float4 bb = s_bb4[a];
    float o0 = bb.x, o1 = bb.y, o2 = bb.z, o3 = bb.w;
#pragma unroll
    for (int k = 0; k < 18; k++) {
        const float4 wq = s_bwq[a * 18 + k];
        const float fv = f[k];
        o0 += fv * wq.x;
        o1 += fv * wq.y;
        o2 += fv * wq.z;
        o3 += fv * wq.w;
    }

    const float SZ[3] = {16.0f, 32.0f, 64.0f};
    const float RI[3] = {0.70710678118654752f, 1.0f, 1.41421356237309505f};
    const float s  = SZ[a / 3];
    const float r  = RI[a % 3];
    const float wa = (s / r) * 0.5f;
    const float ha = (s * r) * 0.5f;
    const float gx = ((float)x + 0.5f) * 50.0f;
    const float gy = ((float)y + 0.5f) * 50.0f;

    const float v0 = fminf(fmaxf(gx - wa + o0, 0.0f), (float)IMG_W);
    const float v1 = fminf(fmaxf(gy - ha + o1, 0.0f), (float)IMG_H);
    const float v2 = fminf(fmaxf(gx + wa + o2, 0.0f), (float)IMG_W);
    const float v3 = fminf(fmaxf(gy + ha + o3, 0.0f), (float)IMG_H);

    s_stage[a * 65 + x] = make_float4(v0 * mval, v1 * mval, v2 * mval, v3 * mval);
    __syncthreads();

    // linearize: out element i (= x*9 + a) <- s_stage[(i%9)*65 + i/9]
    float4* bout = out + (size_t)blockIdx.x * 576;
    const int aa = tid % 9, xx = tid / 9;
    bout[tid] = s_stage[aa * 65 + xx];
}

extern "C" void kernel_launch(void* const* d_in, const int* in_sizes, int n_in,
                              void* d_out, int out_size)
{
    const float* X      = (const float*)d_in[0];
    const float* conv_w = (const float*)d_in[1];
    const float* conv_b = (const float*)d_in[2];
    const float* box_w  = (const float*)d_in[3];
    const float* box_b  = (const float*)d_in[4];
    const float* cls_w  = (const float*)d_in[5];
    const float* cls_b  = (const float*)d_in[6];
    float4* out = (float4*)d_out;

    // 560 blocks (5 chunks x 112 slots) x exactly 12 items each, all resident
    conv1_kernel<<<560, 224>>>(X, conv_w);
    // 672 blocks (one per feature row) x 576 threads (9 anchors x 64 pos)
    head_kernel<<<672, 576>>>(conv_b, box_w, box_b, cls_w, cls_b, out);
}

// round 8
// speedup vs baseline: 1.4848x; 1.0148x over previous
#include <cuda_runtime.h>

#define IMG_H 4200
#define IMG_W 3200
#define HF 84
#define WF 64
#define NB 8
#define ROW_F2 (IMG_W / 2)           // 1600 float2 per image row
#define FEAT (NB * 2 * HF * WF)      // 86016

// conv1 partial sums per 10-row chunk: [chunk][n][ch][ty][tx]  (1.72 MB)
__device__ float g_part[5][FEAT];

// ---------------------------------------------------------------------------
// Kernel 1: 50x50 stride-50 VALID conv, 1->2 ch (non-overlapping patches).
// STREAMING layout: item = (n, ty, chunk) covers 10 CONSECUTIVE image rows
// fully (12.8 KB each) -> each item reads 128 KB perfectly contiguous DRAM.
// Thread t<400 owns f2-cols {t, t+400, t+800, t+1200}; 400 % 25 == 0 so all
// share weight col t%25 -> 10 float4 register weights. 8 accumulators,
// 40 independent LDG.64/item. smem partial reduce, double-buffered,
// ONE barrier per item. 560 blocks x exactly 6 items.
// ---------------------------------------------------------------------------
__global__ __launch_bounds__(416, 2) void conv1_kernel(const float* __restrict__ X,
                                                       const float* __restrict__ w)
{
    __shared__ float s_part[2][2][1600];   // [buf][ch][f2col]  25.6 KB

    const int t = threadIdx.x;
    const bool active = (t < 400);
    const int chunk = blockIdx.x % 5;      // tile rows chunk*10 .. +9
    const int qslot = blockIdx.x / 5;      // 0..111

    // register weights: rows chunk*10+r, f2-col t%25
    const float2* wv0 = (const float2*)w;           // ch0: 1250 f2
    const float2* wv1 = (const float2*)(w + 2500);  // ch1
    const int wc = active ? (t % 25) : 0;
    float4 wr[10];
#pragma unroll
    for (int r = 0; r < 10; r++) {
        const int wi = (chunk * 10 + r) * 25 + wc;
        const float2 p0 = active ? wv0[wi] : make_float2(0.f, 0.f);
        const float2 p1 = active ? wv1[wi] : make_float2(0.f, 0.f);
        wr[r] = make_float4(p0.x, p0.y, p1.x, p1.y);
    }

    int buf = 0;
#pragma unroll 1
    for (int j = 0; j < 6; j++, buf ^= 1) {
        const int ri = qslot * 6 + j;       // feature row index 0..671
        const int n  = ri / HF;
        const int ty = ri % HF;

        if (active) {
            const float2* base = (const float2*)X
                + (size_t)n * (IMG_H * ROW_F2)
                + (size_t)(ty * 50 + chunk * 10) * ROW_F2
                + t;

            float a[8];                      // [colslot k][ch]
#pragma unroll
            for (int i = 0; i < 8; i++) a[i] = 0.f;

#pragma unroll
            for (int r = 0; r < 10; r++) {
#pragma unroll
                for (int k = 0; k < 4; k++) {
                    const float2 xv = __ldg(base + r * ROW_F2 + k * 400);
                    a[k * 2 + 0] += xv.x * wr[r].x + xv.y * wr[r].y;
                    a[k * 2 + 1] += xv.x * wr[r].z + xv.y * wr[r].w;
                }
            }
#pragma unroll
            for (int k = 0; k < 4; k++) {
                s_part[buf][0][t + k * 400] = a[k * 2 + 0];
                s_part[buf][1][t + k * 400] = a[k * 2 + 1];
            }
        }
        __syncthreads();   // only barrier this item (buffers alternate)

        // 128 finalizers: ch = t>>6, tile = t&63 ; sum 25 cols (bank-clean:
        // stride 25 vs 32 banks, gcd=1). Stores = 64-float coalesced runs.
        if (t < 128) {
            const int ch = t >> 6, tile = t & 63;
            float s = 0.f;
#pragma unroll
            for (int m = 0; m < 25; m++) s += s_part[buf][ch][tile * 25 + m];
            g_part[chunk][((n * 2 + ch) * HF + ty) * WF + tile] = s;
        }
    }
    cudaTriggerProgrammaticLaunchCompletion();
}

// ---------------------------------------------------------------------------
// Kernel 2: fused head (R3 shape: 336 blocks x 128 thr, 2 feature rows each).
// PDL: prologue (weights->smem) runs while conv1 drains; gridsync before
// reading g_part; staging sums the 5 chunk partials + bias.
// ---------------------------------------------------------------------------
__global__ __launch_bounds__(128) void head_kernel(const float* __restrict__ conv_b,
                                                   const float* __restrict__ box_w,
                                                   const float* __restrict__ box_b,
                                                   const float* __restrict__ cls_w,
                                                   const float* __restrict__ cls_b,
                                                   float4* __restrict__ out)
{
    __shared__ float  s_bw[36 * 18];       // box_w [36,2,3,3]
    __shared__ float  s_bb[36];
    __shared__ float  s_cw[36];            // cls_w [2,2,3,3]
    __shared__ float  s_cb[2];
    __shared__ float  s_f[2][4][64];       // feats ch x rows(y0-1..y0+2) x cols
    __shared__ float4 s_stage[128 * 9];    // output staging (18 KB)

    const int tid = threadIdx.x;

    for (int i = tid; i < 36 * 18; i += 128) s_bw[i] = box_w[i];
    if (tid < 36) {
        s_bb[tid] = box_b[tid];
        s_cw[tid] = cls_w[tid];
    }
    if (tid < 2) s_cb[tid] = cls_b[tid];

    const int n  = blockIdx.x / 42;
    const int y0 = (blockIdx.x % 42) * 2;   // block covers rows y0, y0+1
    const float cb0 = conv_b[0], cb1 = conv_b[1];

    cudaGridDependencySynchronize();        // conv1's g_part now visible

    // stage feats rows y0-1 .. y0+2 (zero-padded): sum 5 partials + bias
#pragma unroll
    for (int i = 0; i < 4; i++) {
        const int e  = tid + i * 128;       // 0..511
        const int xx = e & 63;
        const int rr = (e >> 6) & 3;        // row y0-1+rr
        const int ic = e >> 8;
        const int yy = y0 - 1 + rr;
        float v = 0.0f;
        if (yy >= 0 && yy < HF) {
            const int idx = ((n * 2 + ic) * HF + yy) * WF + xx;
            v = ic ? cb1 : cb0;
#pragma unroll
            for (int c = 0; c < 5; c++) v += g_part[c][idx];
        }
        s_f[ic][rr][xx] = v;
    }
    __syncthreads();

    const int x  = tid & 63;
    const int ly = tid >> 6;                // 0 or 1
    const int y  = y0 + ly;

    // gather 3x3x2 neighborhood from smem (x edges zero-padded)
    float f[18];
#pragma unroll
    for (int ic = 0; ic < 2; ic++) {
#pragma unroll
        for (int dy = 0; dy < 3; dy++) {
#pragma unroll
            for (int dx = 0; dx < 3; dx++) {
                const int xx = x + dx - 1;
                float v = 0.0f;
                if (xx >= 0 && xx < WF) v = s_f[ic][ly + dy][xx];
                f[ic * 9 + dy * 3 + dx] = v;
            }
        }
    }

    // cls conv + 2-channel softmax threshold
    float c0 = s_cb[0], c1 = s_cb[1];
#pragma unroll
    for (int k = 0; k < 18; k++) {
        c0 += f[k] * s_cw[k];
        c1 += f[k] * s_cw[18 + k];
    }
    const float m  = fmaxf(c0, c1);
    const float e0 = __expf(c0 - m), e1 = __expf(c1 - m);
    const float p1 = e1 / (e0 + e1);
    const float mval = (p1 > 0.95f) ? 1.0f : 0.0f;

    const float gx = ((float)x + 0.5f) * 50.0f;
    const float gy = ((float)y + 0.5f) * 50.0f;
    const float SZ[3] = {16.0f, 32.0f, 64.0f};
    const float RI[3] = {0.70710678118654752f, 1.0f, 1.41421356237309505f};

#pragma unroll
    for (int a = 0; a < 9; a++) {
        float o0 = s_bb[a * 4 + 0], o1 = s_bb[a * 4 + 1];
        float o2 = s_bb[a * 4 + 2], o3 = s_bb[a * 4 + 3];
        const float* wp = &s_bw[a * 4 * 18];
#pragma unroll
        for (int kk = 0; kk < 18; kk++) {
            const float fv = f[kk];
            o0 += fv * wp[kk];
            o1 += fv * wp[18 + kk];
            o2 += fv * wp[36 + kk];
            o3 += fv * wp[54 + kk];
        }
        const float s  = SZ[a / 3];
        const float r  = RI[a % 3];
        const float wa = (s / r) * 0.5f;
        const float ha = (s * r) * 0.5f;
        float v0 = fminf(fmaxf(gx - wa + o0, 0.0f), (float)IMG_W);
        float v1 = fminf(fmaxf(gy - ha + o1, 0.0f), (float)IMG_H);
        float v2 = fminf(fmaxf(gx + wa + o2, 0.0f), (float)IMG_W);
        float v3 = fminf(fmaxf(gy + ha + o3, 0.0f), (float)IMG_H);
        s_stage[tid * 9 + a] =
            make_float4(v0 * mval, v1 * mval, v2 * mval, v3 * mval);
    }
    __syncthreads();

    // coalesced copy-out: block's 128 positions = 1152 contiguous float4
    float4* bout = out + (size_t)blockIdx.x * 128 * 9;
#pragma unroll
    for (int i = 0; i < 9; i++)
        bout[tid + 128 * i] = s_stage[tid + 128 * i];
}

extern "C" void kernel_launch(void* const* d_in, const int* in_sizes, int n_in,
                              void* d_out, int out_size)
{
    const float* X      = (const float*)d_in[0];
    const float* conv_w = (const float*)d_in[1];
    const float* conv_b = (const float*)d_in[2];
    const float* box_w  = (const float*)d_in[3];
    const float* box_b  = (const float*)d_in[4];
    const float* cls_w  = (const float*)d_in[5];
    const float* cls_b  = (const float*)d_in[6];
    float4* out = (float4*)d_out;

    // 560 blocks (5 chunks x 112 qslots) x exactly 6 streaming items
    conv1_kernel<<<560, 416>>>(X, conv_w);

    // head with programmatic dependent launch (prologue overlaps conv1 drain)
    cudaLaunchConfig_t cfg = {};
    cfg.gridDim  = dim3(336, 1, 1);
    cfg.blockDim = dim3(128, 1, 1);
    cfg.dynamicSmemBytes = 0;
    cfg.stream = 0;
    cudaLaunchAttribute attrs[1];
    attrs[0].id = cudaLaunchAttributeProgrammaticStreamSerialization;
    attrs[0].val.programmaticStreamSerializationAllowed = 1;
    cfg.attrs = attrs;
    cfg.numAttrs = 1;
    cudaLaunchKernelEx(&cfg, head_kernel, conv_b, box_w, box_b, cls_w, cls_b, out);
}

// round 9
// speedup vs baseline: 1.4962x; 1.0076x over previous
#include <cuda_runtime.h>

#define IMG_H 4200
#define IMG_W 3200
#define HF 84
#define WF 64
#define NB 8
#define ROW_F2 (IMG_W / 2)           // 1600 float2 per image row
#define FEAT (NB * 2 * HF * WF)      // 86016
#define N_ROWS (NB * HF)             // 672 feature rows

// conv1 partial sums per 10-row chunk: [chunk][n][ch][ty][tx]  (1.72 MB)
__device__ float g_part[5][FEAT];
// dynamic work queue: one ticket counter per weight-chunk
__device__ unsigned g_tickets[5];

__global__ void init_kernel()
{
    if (threadIdx.x < 5) g_tickets[threadIdx.x] = 0;
}

// ---------------------------------------------------------------------------
// Kernel 1: 50x50 stride-50 VALID conv, 1->2 ch (non-overlapping patches).
// Item = (chunk, feature row): 10 consecutive image rows, 128 KB contiguous.
// Thread t<400 owns f2-cols {t,t+400,t+800,t+1200} (shared weight col t%25
// -> 10 float4 register weights). DYNAMIC per-chunk ticket queue with
// prefetch: single wave (295 blocks < 296 resident), work-stealing absorbs
// per-CTA completion spread. One barrier per item.
// ---------------------------------------------------------------------------
__global__ __launch_bounds__(416, 2) void conv1_kernel(const float* __restrict__ X,
                                                       const float* __restrict__ w)
{
    __shared__ float    s_part[2][2][1600];   // [buf][ch][f2col]  25.6 KB
    __shared__ unsigned s_ri[2];

    const int t = threadIdx.x;
    const bool active = (t < 400);
    const int chunk = blockIdx.x % 5;         // tile rows chunk*10 .. +9

    // register weights: rows chunk*10+r, f2-col t%25
    const float2* wv0 = (const float2*)w;           // ch0: 1250 f2
    const float2* wv1 = (const float2*)(w + 2500);  // ch1
    const int wc = active ? (t % 25) : 0;
    float4 wr[10];
#pragma unroll
    for (int r = 0; r < 10; r++) {
        const int wi = (chunk * 10 + r) * 25 + wc;
        const float2 p0 = active ? wv0[wi] : make_float2(0.f, 0.f);
        const float2 p1 = active ? wv1[wi] : make_float2(0.f, 0.f);
        wr[r] = make_float4(p0.x, p0.y, p1.x, p1.y);
    }

    if (t == 0) s_ri[0] = atomicAdd(&g_tickets[chunk], 1u);
    __syncthreads();

#pragma unroll 1
    for (int j = 0; ; j++) {
        const int buf = j & 1;
        const unsigned ri = s_ri[buf];        // uniform across block
        if (ri >= N_ROWS) break;

        if (t == 0) s_ri[buf ^ 1] = atomicAdd(&g_tickets[chunk], 1u);  // prefetch

        const int n  = ri / HF;
        const int ty = ri % HF;

        if (active) {
            const float2* base = (const float2*)X
                + (size_t)n * (IMG_H * ROW_F2)
                + (size_t)(ty * 50 + chunk * 10) * ROW_F2
                + t;

            float a[8];                        // [colslot k][ch]
#pragma unroll
            for (int i = 0; i < 8; i++) a[i] = 0.f;

#pragma unroll
            for (int r = 0; r < 10; r++) {
#pragma unroll
                for (int k = 0; k < 4; k++) {
                    const float2 xv = __ldg(base + r * ROW_F2 + k * 400);
                    a[k * 2 + 0] += xv.x * wr[r].x + xv.y * wr[r].y;
                    a[k * 2 + 1] += xv.x * wr[r].z + xv.y * wr[r].w;
                }
            }
#pragma unroll
            for (int k = 0; k < 4; k++) {
                s_part[buf][0][t + k * 400] = a[k * 2 + 0];
                s_part[buf][1][t + k * 400] = a[k * 2 + 1];
            }
        }
        __syncthreads();   // s_part[buf] + next ticket ready; prev buf free

        // 128 finalizers: ch = t>>6, tile = t&63 (stride-25 smem reads are
        // bank-clean; 64-float coalesced g_part stores)
        if (t < 128) {
            const int ch = t >> 6, tile = t & 63;
            float s = 0.f;
#pragma unroll
            for (int m = 0; m < 25; m++) s += s_part[buf][ch][tile * 25 + m];
            g_part[chunk][((n * 2 + ch) * HF + ty) * WF + tile] = s;
        }
    }
    cudaTriggerProgrammaticLaunchCompletion();
}

// ---------------------------------------------------------------------------
// Kernel 2: fused head. Block = 2 feature rows x 256 threads: tid -> position
// (x, ly) and anchor-half (warp-uniform). PDL prologue overlaps conv1 drain.
// Staging sums the 5 conv1 chunk partials + bias.
// ---------------------------------------------------------------------------
__global__ __launch_bounds__(256) void head_kernel(const float* __restrict__ conv_b,
                                                   const float* __restrict__ box_w,
                                                   const float* __restrict__ box_b,
                                                   const float* __restrict__ cls_w,
                                                   const float* __restrict__ cls_b,
                                                   float4* __restrict__ out)
{
    __shared__ float  s_bw[36 * 18];       // box_w [36,2,3,3]
    __shared__ float  s_bb[36];
    __shared__ float  s_cw[36];            // cls_w [2,2,3,3]
    __shared__ float  s_cb[2];
    __shared__ float  s_f[2][4][64];       // feats ch x rows(y0-1..y0+2) x cols
    __shared__ float4 s_stage[128 * 9];    // output staging (18 KB)

    const int tid = threadIdx.x;

    for (int i = tid; i < 36 * 18; i += 256) s_bw[i] = box_w[i];
    if (tid < 36) {
        s_bb[tid] = box_b[tid];
        s_cw[tid] = cls_w[tid];
    }
    if (tid < 2) s_cb[tid] = cls_b[tid];

    const int n  = blockIdx.x / 42;
    const int y0 = (blockIdx.x % 42) * 2;   // block covers rows y0, y0+1
    const float cb0 = conv_b[0], cb1 = conv_b[1];

    cudaGridDependencySynchronize();        // conv1's g_part now visible

    // stage feats rows y0-1 .. y0+2 (zero-padded): sum 5 partials + bias
#pragma unroll
    for (int i = 0; i < 2; i++) {
        const int e  = tid + i * 256;       // 0..511
        const int xx = e & 63;
        const int rr = (e >> 6) & 3;        // row y0-1+rr
        const int ic = e >> 8;
        const int yy = y0 - 1 + rr;
        float v = 0.0f;
        if (yy >= 0 && yy < HF) {
            const int idx = ((n * 2 + ic) * HF + yy) * WF + xx;
            v = ic ? cb1 : cb0;
#pragma unroll
            for (int c = 0; c < 5; c++) v += g_part[c][idx];
        }
        s_f[ic][rr][xx] = v;
    }
    __syncthreads();

    const int x    = tid & 63;
    const int ly   = (tid >> 6) & 1;        // row within block
    const int half = tid >> 7;              // anchor half (warp-uniform)
    const int y    = y0 + ly;
    const int pos  = ly * 64 + x;           // 0..127

    // gather 3x3x2 neighborhood from smem (x edges zero-padded)
    float f[18];
#pragma unroll
    for (int ic = 0; ic < 2; ic++) {
#pragma unroll
        for (int dy = 0; dy < 3; dy++) {
#pragma unroll
            for (int dx = 0; dx < 3; dx++) {
                const int xx = x + dx - 1;
                float v = 0.0f;
                if (xx >= 0 && xx < WF) v = s_f[ic][ly + dy][xx];
                f[ic * 9 + dy * 3 + dx] = v;
            }
        }
    }

    // cls conv + 2-channel softmax threshold (computed by both halves)
    float c0 = s_cb[0], c1 = s_cb[1];
#pragma unroll
    for (int k = 0; k < 18; k++) {
        c0 += f[k] * s_cw[k];
        c1 += f[k] * s_cw[18 + k];
    }
    const float m  = fmaxf(c0, c1);
    const float e0 = __expf(c0 - m), e1 = __expf(c1 - m);
    const float p1 = e1 / (e0 + e1);
    const float mval = (p1 > 0.95f) ? 1.0f : 0.0f;

    const float gx = ((float)x + 0.5f) * 50.0f;
    const float gy = ((float)y + 0.5f) * 50.0f;
    const float SZ[3] = {16.0f, 32.0f, 64.0f};
    const float RI[3] = {0.70710678118654752f, 1.0f, 1.41421356237309505f};

    // half 0: anchors 0..4, half 1: anchors 5..8 (uniform predicate)
#pragma unroll
    for (int aa = 0; aa < 5; aa++) {
        const int a = half * 5 + aa;
        if (a < 9) {
            float o0 = s_bb[a * 4 + 0], o1 = s_bb[a * 4 + 1];
            float o2 = s_bb[a * 4 + 2], o3 = s_bb[a * 4 + 3];
            const float* wp = &s_bw[a * 4 * 18];
#pragma unroll
            for (int kk = 0; kk < 18; kk++) {
                const float fv = f[kk];
                o0 += fv * wp[kk];
                o1 += fv * wp[18 + kk];
                o2 += fv * wp[36 + kk];
                o3 += fv * wp[54 + kk];
            }
            const float s  = SZ[a / 3];
            const float r  = RI[a % 3];
            const float wa = (s / r) * 0.5f;
            const float ha = (s * r) * 0.5f;
            float v0 = fminf(fmaxf(gx - wa + o0, 0.0f), (float)IMG_W);
            float v1 = fminf(fmaxf(gy - ha + o1, 0.0f), (float)IMG_H);
            float v2 = fminf(fmaxf(gx + wa + o2, 0.0f), (float)IMG_W);
            float v3 = fminf(fmaxf(gy + ha + o3, 0.0f), (float)IMG_H);
            s_stage[pos * 9 + a] =
                make_float4(v0 * mval, v1 * mval, v2 * mval, v3 * mval);
        }
    }
    __syncthreads();

    // coalesced copy-out: block's 128 positions = 1152 contiguous float4
    float4* bout = out + (size_t)blockIdx.x * 128 * 9;
    for (int i = tid; i < 1152; i += 256)
        bout[i] = s_stage[i];
}

extern "C" void kernel_launch(void* const* d_in, const int* in_sizes, int n_in,
                              void* d_out, int out_size)
{
    const float* X      = (const float*)d_in[0];
    const float* conv_w = (const float*)d_in[1];
    const float* conv_b = (const float*)d_in[2];
    const float* box_w  = (const float*)d_in[3];
    const float* box_b  = (const float*)d_in[4];
    const float* cls_w  = (const float*)d_in[5];
    const float* cls_b  = (const float*)d_in[6];
    float4* out = (float4*)d_out;

    // reset work-queue counters (runs on every graph replay)
    init_kernel<<<1, 32>>>();

    // 295 blocks (59 per chunk) -- strictly single wave, dynamic tickets
    conv1_kernel<<<295, 416>>>(X, conv_w);

    // head with programmatic dependent launch (prologue overlaps conv1 drain)
    cudaLaunchConfig_t cfg = {};
    cfg.gridDim  = dim3(336, 1, 1);
    cfg.blockDim = dim3(256, 1, 1);
    cfg.dynamicSmemBytes = 0;
    cfg.stream = 0;
    cudaLaunchAttribute attrs[1];
    attrs[0].id = cudaLaunchAttributeProgrammaticStreamSerialization;
    attrs[0].val.programmaticStreamSerializationAllowed = 1;
    cfg.attrs = attrs;
    cfg.numAttrs = 1;
    cudaLaunchKernelEx(&cfg, head_kernel, conv_b, box_w, box_b, cls_w, cls_b, out);
}

// round 10
// speedup vs baseline: 1.5231x; 1.0180x over previous
#include <cuda_runtime.h>

#define IMG_H 4200
#define IMG_W 3200
#define HF 84
#define WF 64
#define NB 8
#define ROW_F2 (IMG_W / 2)           // 1600 float2 per image row
#define FEAT (NB * 2 * HF * WF)      // 86016
#define N_ROWS (NB * HF)             // 672 feature rows

// conv1 partial sums per 10-row chunk: [chunk][n][ch][ty][tx]  (1.72 MB)
__device__ float g_part[5][FEAT];
// dynamic work queue: one ticket counter per weight-chunk.
// Zero-initialized at load; RESET BY head_kernel at the end of every launch,
// so the invariant "tickets == 0 on kernel_launch entry" holds for the
// correctness call and every graph replay. No init kernel needed.
__device__ unsigned g_tickets[5];

// ---------------------------------------------------------------------------
// Kernel 1: 50x50 stride-50 VALID conv, 1->2 ch (non-overlapping patches).
// Item = (chunk, feature row): 10 consecutive image rows, 128 KB contiguous.
// Thread t<400 owns f2-cols {t,t+400,t+800,t+1200} (shared weight col t%25
// -> 10 float4 register weights). DYNAMIC per-chunk ticket queue with
// prefetch: single wave (295 blocks < 296 resident), work-stealing absorbs
// per-CTA completion spread. One barrier per item. Output mapping per item
// is fixed -> bitwise deterministic regardless of ticket assignment.
// ---------------------------------------------------------------------------
__global__ __launch_bounds__(416, 2) void conv1_kernel(const float* __restrict__ X,
                                                       const float* __restrict__ w)
{
    __shared__ float    s_part[2][2][1600];   // [buf][ch][f2col]  25.6 KB
    __shared__ unsigned s_ri[2];

    const int t = threadIdx.x;
    const bool active = (t < 400);
    const int chunk = blockIdx.x % 5;         // tile rows chunk*10 .. +9

    // register weights: rows chunk*10+r, f2-col t%25
    const float2* wv0 = (const float2*)w;           // ch0: 1250 f2
    const float2* wv1 = (const float2*)(w + 2500);  // ch1
    const int wc = active ? (t % 25) : 0;
    float4 wr[10];
#pragma unroll
    for (int r = 0; r < 10; r++) {
        const int wi = (chunk * 10 + r) * 25 + wc;
        const float2 p0 = active ? wv0[wi] : make_float2(0.f, 0.f);
        const float2 p1 = active ? wv1[wi] : make_float2(0.f, 0.f);
        wr[r] = make_float4(p0.x, p0.y, p1.x, p1.y);
    }

    if (t == 0) s_ri[0] = atomicAdd(&g_tickets[chunk], 1u);
    __syncthreads();

#pragma unroll 1
    for (int j = 0; ; j++) {
        const int buf = j & 1;
        const unsigned ri = s_ri[buf];        // uniform across block
        if (ri >= N_ROWS) break;

        if (t == 0) s_ri[buf ^ 1] = atomicAdd(&g_tickets[chunk], 1u);  // prefetch

        const int n  = ri / HF;
        const int ty = ri % HF;

        if (active) {
            const float2* base = (const float2*)X
                + (size_t)n * (IMG_H * ROW_F2)
                + (size_t)(ty * 50 + chunk * 10) * ROW_F2
                + t;

            float a[8];                        // [colslot k][ch]
#pragma unroll
            for (int i = 0; i < 8; i++) a[i] = 0.f;

#pragma unroll
            for (int r = 0; r < 10; r++) {
#pragma unroll
                for (int k = 0; k < 4; k++) {
                    const float2 xv = __ldg(base + r * ROW_F2 + k * 400);
                    a[k * 2 + 0] += xv.x * wr[r].x + xv.y * wr[r].y;
                    a[k * 2 + 1] += xv.x * wr[r].z + xv.y * wr[r].w;
                }
            }
#pragma unroll
            for (int k = 0; k < 4; k++) {
                s_part[buf][0][t + k * 400] = a[k * 2 + 0];
                s_part[buf][1][t + k * 400] = a[k * 2 + 1];
            }
        }
        __syncthreads();   // s_part[buf] + next ticket ready; prev buf free

        // 128 finalizers: ch = t>>6, tile = t&63 (stride-25 smem reads are
        // bank-clean; 64-float coalesced g_part stores)
        if (t < 128) {
            const int ch = t >> 6, tile = t & 63;
            float s = 0.f;
#pragma unroll
            for (int m = 0; m < 25; m++) s += s_part[buf][ch][tile * 25 + m];
            g_part[chunk][((n * 2 + ch) * HF + ty) * WF + tile] = s;
        }
    }
    cudaTriggerProgrammaticLaunchCompletion();
}

// ---------------------------------------------------------------------------
// Kernel 2: fused head. Block = 2 feature rows x 256 threads: tid -> position
// (x, ly) and anchor-half (warp-uniform). PDL prologue overlaps conv1 drain.
// Staging sums the 5 conv1 chunk partials + bias. Also resets the work-queue
// tickets for the next launch (after gridsync, conv1 is fully done).
// ---------------------------------------------------------------------------
__global__ __launch_bounds__(256) void head_kernel(const float* __restrict__ conv_b,
                                                   const float* __restrict__ box_w,
                                                   const float* __restrict__ box_b,
                                                   const float* __restrict__ cls_w,
                                                   const float* __restrict__ cls_b,
                                                   float4* __restrict__ out)
{
    __shared__ float  s_bw[36 * 18];       // box_w [36,2,3,3]
    __shared__ float  s_bb[36];
    __shared__ float  s_cw[36];            // cls_w [2,2,3,3]
    __shared__ float  s_cb[2];
    __shared__ float  s_f[2][4][64];       // feats ch x rows(y0-1..y0+2) x cols
    __shared__ float4 s_stage[128 * 9];    // output staging (18 KB)

    const int tid = threadIdx.x;

    for (int i = tid; i < 36 * 18; i += 256) s_bw[i] = box_w[i];
    if (tid < 36) {
        s_bb[tid] = box_b[tid];
        s_cw[tid] = cls_w[tid];
    }
    if (tid < 2) s_cb[tid] = cls_b[tid];

    const int n  = blockIdx.x / 42;
    const int y0 = (blockIdx.x % 42) * 2;   // block covers rows y0, y0+1
    const float cb0 = conv_b[0], cb1 = conv_b[1];

    cudaGridDependencySynchronize();        // conv1's g_part now visible

    // reset work-queue tickets for the next launch (conv1 provably done)
    if (blockIdx.x == 0 && tid < 5) g_tickets[tid] = 0;

    // stage feats rows y0-1 .. y0+2 (zero-padded): sum 5 partials + bias
#pragma unroll
    for (int i = 0; i < 2; i++) {
        const int e  = tid + i * 256;       // 0..511
        const int xx = e & 63;
        const int rr = (e >> 6) & 3;        // row y0-1+rr
        const int ic = e >> 8;
        const int yy = y0 - 1 + rr;
        float v = 0.0f;
        if (yy >= 0 && yy < HF) {
            const int idx = ((n * 2 + ic) * HF + yy) * WF + xx;
            v = ic ? cb1 : cb0;
#pragma unroll
            for (int c = 0; c < 5; c++) v += g_part[c][idx];
        }
        s_f[ic][rr][xx] = v;
    }
    __syncthreads();

    const int x    = tid & 63;
    const int ly   = (tid >> 6) & 1;        // row within block
    const int half = tid >> 7;              // anchor half (warp-uniform)
    const int y    = y0 + ly;
    const int pos  = ly * 64 + x;           // 0..127

    // gather 3x3x2 neighborhood from smem (x edges zero-padded)
    float f[18];
#pragma unroll
    for (int ic = 0; ic < 2; ic++) {
#pragma unroll
        for (int dy = 0; dy < 3; dy++) {
#pragma unroll
            for (int dx = 0; dx < 3; dx++) {
                const int xx = x + dx - 1;
                float v = 0.0f;
                if (xx >= 0 && xx < WF) v = s_f[ic][ly + dy][xx];
                f[ic * 9 + dy * 3 + dx] = v;
            }
        }
    }

    // cls conv + 2-channel softmax threshold (computed by both halves)
    float c0 = s_cb[0], c1 = s_cb[1];
#pragma unroll
    for (int k = 0; k < 18; k++) {
        c0 += f[k] * s_cw[k];
        c1 += f[k] * s_cw[18 + k];
    }
    const float m  = fmaxf(c0, c1);
    const float e0 = __expf(c0 - m), e1 = __expf(c1 - m);
    const float p1 = e1 / (e0 + e1);
    const float mval = (p1 > 0.95f) ? 1.0f : 0.0f;

    const float gx = ((float)x + 0.5f) * 50.0f;
    const float gy = ((float)y + 0.5f) * 50.0f;
    const float SZ[3] = {16.0f, 32.0f, 64.0f};
    const float RI[3] = {0.70710678118654752f, 1.0f, 1.41421356237309505f};

    // half 0: anchors 0..4, half 1: anchors 5..8 (uniform predicate)
#pragma unroll
    for (int aa = 0; aa < 5; aa++) {
        const int a = half * 5 + aa;
        if (a < 9) {
            float o0 = s_bb[a * 4 + 0], o1 = s_bb[a * 4 + 1];
            float o2 = s_bb[a * 4 + 2], o3 = s_bb[a * 4 + 3];
            const float* wp = &s_bw[a * 4 * 18];
#pragma unroll
            for (int kk = 0; kk < 18; kk++) {
                const float fv = f[kk];
                o0 += fv * wp[kk];
                o1 += fv * wp[18 + kk];
                o2 += fv * wp[36 + kk];
                o3 += fv * wp[54 + kk];
            }
            const float s  = SZ[a / 3];
            const float r  = RI[a % 3];
            const float wa = (s / r) * 0.5f;
            const float ha = (s * r) * 0.5f;
            float v0 = fminf(fmaxf(gx - wa + o0, 0.0f), (float)IMG_W);
            float v1 = fminf(fmaxf(gy - ha + o1, 0.0f), (float)IMG_H);
            float v2 = fminf(fmaxf(gx + wa + o2, 0.0f), (float)IMG_W);
            float v3 = fminf(fmaxf(gy + ha + o3, 0.0f), (float)IMG_H);
            s_stage[pos * 9 + a] =
                make_float4(v0 * mval, v1 * mval, v2 * mval, v3 * mval);
        }
    }
    __syncthreads();

    // coalesced copy-out: block's 128 positions = 1152 contiguous float4
    float4* bout = out + (size_t)blockIdx.x * 128 * 9;
    for (int i = tid; i < 1152; i += 256)
        bout[i] = s_stage[i];
}

extern "C" void kernel_launch(void* const* d_in, const int* in_sizes, int n_in,
                              void* d_out, int out_size)
{
    const float* X      = (const float*)d_in[0];
    const float* conv_w = (const float*)d_in[1];
    const float* conv_b = (const float*)d_in[2];
    const float* box_w  = (const float*)d_in[3];
    const float* box_b  = (const float*)d_in[4];
    const float* cls_w  = (const float*)d_in[5];
    const float* cls_b  = (const float*)d_in[6];
    float4* out = (float4*)d_out;

    // 295 blocks (59 per chunk) -- strictly single wave, dynamic tickets
    // (tickets are 0 here: zero-init at load, reset by head_kernel each launch)
    conv1_kernel<<<295, 416>>>(X, conv_w);

    // head with programmatic dependent launch (prologue overlaps conv1 drain)
    cudaLaunchConfig_t cfg = {};
    cfg.gridDim  = dim3(336, 1, 1);
    cfg.blockDim = dim3(256, 1, 1);
    cfg.dynamicSmemBytes = 0;
    cfg.stream = 0;
    cudaLaunchAttribute attrs[1];
    attrs[0].id = cudaLaunchAttributeProgrammaticStreamSerialization;
    attrs[0].val.programmaticStreamSerializationAllowed = 1;
    cfg.attrs = attrs;
    cfg.numAttrs = 1;
    cudaLaunchKernelEx(&cfg, head_kernel, conv_b, box_w, box_b, cls_w, cls_b, out);
}